// round 5
// baseline (speedup 1.0000x reference)
#include <cuda_runtime.h>
#include <cuda_fp16.h>

#define B_ 32
#define N_ 16384
#define D_ 256
#define S_ 8
#define CHUNKS 64
#define ROWS_PER_BLOCK (N_ / CHUNKS)   // 256
#define THREADS 256                    // 8 warps
#define EPSN 1e-12f
#define CAP 16                         // per-block candidate capacity
#define MAXC 512                       // select-side candidate capacity

// ---- scratch (device globals: no allocations allowed) ----
__device__ float  g_score[B_ * N_];                 // running score (approx after s>0)
__device__ __half g_fnorm[(size_t)B_ * N_ * D_];    // normalized rows, fp16 (256 MB)
__device__ float  g_selhist[(size_t)S_ * B_ * D_];  // exact fp32 selnorm history
__device__ float  g_salmax[B_];                     // exact max saliency per batch
__device__ float  g_pval[B_ * CHUNKS];              // per-block max score
__device__ int    g_pidx[B_ * CHUNKS];              // per-block argmax idx (exact, from pre)
__device__ int    g_ccnt[B_ * CHUNKS];              // per-block candidate count
__device__ int    g_cand[B_ * CHUNKS * CAP];        // per-block candidate rows

// Block-wide sum; every thread returns the same value (deterministic order).
__device__ __forceinline__ float block_reduce_sum(float v, float* red) {
    int lane = threadIdx.x & 31, warp = threadIdx.x >> 5;
    #pragma unroll
    for (int o = 16; o; o >>= 1) v += __shfl_xor_sync(0xffffffffu, v, o);
    if (lane == 0) red[warp] = v;
    __syncthreads();
    float tot = red[0] + red[1] + red[2] + red[3]
              + red[4] + red[5] + red[6] + red[7];
    __syncthreads();
    return tot;
}

// -----------------------------------------------------------------------------
// Pass 0: exact fp32 row norms -> score, fnorm fp16, exact per-block argmax.
// 4-row batching for MLP. grid = B*CHUNKS x 256.
// -----------------------------------------------------------------------------
__global__ void pre_kernel(const float* __restrict__ f) {
    int blk  = blockIdx.x;
    int b    = blk / CHUNKS;
    int c    = blk % CHUNKS;
    int warp = threadIdx.x >> 5;
    int lane = threadIdx.x & 31;
    int row0 = c * ROWS_PER_BLOCK + warp * 32;

    float bestV = -1.0f;
    int   bestI = 0x7fffffff;

    for (int g = 0; g < 8; ++g) {
        float4 a[4], bb[4];
        size_t base0 = ((size_t)b * N_ + row0 + g * 4) * D_;
        #pragma unroll
        for (int r = 0; r < 4; ++r) {
            const float4* p = (const float4*)(f + base0 + (size_t)r * D_);
            a[r]  = p[2 * lane];
            bb[r] = p[2 * lane + 1];
        }
        float s[4];
        #pragma unroll
        for (int r = 0; r < 4; ++r)
            s[r] = a[r].x*a[r].x + a[r].y*a[r].y + a[r].z*a[r].z + a[r].w*a[r].w
                 + bb[r].x*bb[r].x + bb[r].y*bb[r].y + bb[r].z*bb[r].z + bb[r].w*bb[r].w;
        #pragma unroll
        for (int o = 16; o; o >>= 1) {
            #pragma unroll
            for (int r = 0; r < 4; ++r) s[r] += __shfl_xor_sync(0xffffffffu, s[r], o);
        }
        #pragma unroll
        for (int r = 0; r < 4; ++r) {
            int   row = row0 + g * 4 + r;
            float nrm = sqrtf(s[r]);
            float inv = 1.0f / fmaxf(nrm, EPSN);
            union { float4 v; __half2 h[4]; } u;
            u.h[0] = __floats2half2_rn(a[r].x * inv,  a[r].y * inv);
            u.h[1] = __floats2half2_rn(a[r].z * inv,  a[r].w * inv);
            u.h[2] = __floats2half2_rn(bb[r].x * inv, bb[r].y * inv);
            u.h[3] = __floats2half2_rn(bb[r].z * inv, bb[r].w * inv);
            *(float4*)(g_fnorm + base0 + (size_t)r * D_ + (size_t)lane * 8) = u.v;
            if (lane == 0) g_score[b * N_ + row] = nrm;
            if (nrm > bestV) { bestV = nrm; bestI = row; }
        }
    }

    __shared__ float sv[8];
    __shared__ int   si[8];
    if (lane == 0) { sv[warp] = bestV; si[warp] = bestI; }
    __syncthreads();
    if (threadIdx.x == 0) {
        float v = sv[0]; int i = si[0];
        #pragma unroll
        for (int w = 1; w < 8; ++w)
            if (sv[w] > v || (sv[w] == v && si[w] < i)) { v = sv[w]; i = si[w]; }
        g_pval[blk] = v;
        g_pidx[blk] = i;
    }
}

// -----------------------------------------------------------------------------
// Update (suppression for slot s): 8-row batching, fused block max + candidate
// recording for the NEXT select (margin vs block-local max = provable superset
// of global-margin set). grid = B*CHUNKS x 256.
// -----------------------------------------------------------------------------
__global__ void update_kernel(int s) {
    int blk  = blockIdx.x;
    int b    = blk / CHUNKS;
    int c    = blk % CHUNKS;
    int t    = threadIdx.x;
    int warp = t >> 5;
    int lane = t & 31;

    __shared__ float ssel[D_];
    __shared__ float s_scores[THREADS];   // score of row c*256 + i at slot s+1
    __shared__ float s_wmax[8];
    __shared__ float s_thr;
    __shared__ int   s_cnt;

    ssel[t] = g_selhist[((size_t)s * B_ + b) * D_ + t];
    __syncthreads();

    float se[8];
    #pragma unroll
    for (int k = 0; k < 8; ++k) se[k] = ssel[lane * 8 + k];

    int row0 = c * ROWS_PER_BLOCK + warp * 32;
    float bestV = -1.0f;

    for (int g = 0; g < 4; ++g) {
        size_t base0 = ((size_t)b * N_ + row0 + g * 8) * D_;
        float4 raw[8];
        float  sc[8];
        #pragma unroll
        for (int r = 0; r < 8; ++r)
            raw[r] = *(const float4*)(g_fnorm + base0 + (size_t)r * D_ + (size_t)lane * 8);
        #pragma unroll
        for (int r = 0; r < 8; ++r)
            sc[r] = g_score[b * N_ + row0 + g * 8 + r];

        float d[8];
        #pragma unroll
        for (int r = 0; r < 8; ++r) {
            __half2* h = (__half2*)&raw[r];
            float acc = 0.0f;
            #pragma unroll
            for (int k = 0; k < 4; ++k) {
                float2 f2 = __half22float2(h[k]);
                acc = fmaf(f2.x, se[2 * k],     acc);
                acc = fmaf(f2.y, se[2 * k + 1], acc);
            }
            d[r] = acc;
        }
        #pragma unroll
        for (int o = 16; o; o >>= 1) {
            #pragma unroll
            for (int r = 0; r < 8; ++r) d[r] += __shfl_xor_sync(0xffffffffu, d[r], o);
        }
        #pragma unroll
        for (int r = 0; r < 8; ++r) {
            float ns = sc[r] * (1.0f - fminf(fmaxf(d[r], 0.0f), 1.0f));
            if (lane == 0) {
                g_score[b * N_ + row0 + g * 8 + r] = ns;
                s_scores[warp * 32 + g * 8 + r]    = ns;
            }
            bestV = fmaxf(bestV, ns);
        }
    }

    if (lane == 0) s_wmax[warp] = bestV;
    __syncthreads();
    if (t == 0) {
        float m = s_wmax[0];
        #pragma unroll
        for (int w = 1; w < 8; ++w) m = fmaxf(m, s_wmax[w]);
        // margin for select(s+1): rigorous 2*eps bound with 3x headroom
        float margin = g_salmax[b] * (float)(s + 1) * 3e-3f;
        s_thr = m - margin;
        s_cnt = 0;
        g_pval[blk] = m;
    }
    __syncthreads();

    // s_scores[i] corresponds to row c*256 + i
    if (s_scores[t] >= s_thr) {
        int p = atomicAdd(&s_cnt, 1);
        if (p < CAP) g_cand[blk * CAP + p] = c * ROWS_PER_BLOCK + t;
    }
    __syncthreads();
    if (t == 0) g_ccnt[blk] = s_cnt;   // > CAP signals overflow
}

// -----------------------------------------------------------------------------
// Select(slot): parallel partial-max reduce; gather pre-recorded candidates;
// exact fp32 verification only when >1 candidate. grid = B x 256.
// -----------------------------------------------------------------------------
__global__ void select_kernel(const float* __restrict__ f,
                              float* __restrict__ out, int slot) {
    int b = blockIdx.x;
    int t = threadIdx.x;

    __shared__ float red[8];
    __shared__ float s_gv;
    __shared__ int   s_gi;
    __shared__ int   s_cnt, s_ovf;
    __shared__ int   list[MAXC];
    __shared__ float s_bestV;
    __shared__ int   s_bestI;

    // Parallel reduce of 64 per-block partials (val, idx) with low-idx tiebreak.
    if (t < 32) {
        float v  = g_pval[b * CHUNKS + t];      int i  = g_pidx[b * CHUNKS + t];
        float v2 = g_pval[b * CHUNKS + t + 32]; int i2 = g_pidx[b * CHUNKS + t + 32];
        if (v2 > v || (v2 == v && i2 < i)) { v = v2; i = i2; }
        #pragma unroll
        for (int o = 16; o; o >>= 1) {
            float ov = __shfl_xor_sync(0xffffffffu, v, o);
            int   oi = __shfl_xor_sync(0xffffffffu, i, o);
            if (ov > v || (ov == v && oi < i)) { v = ov; i = oi; }
        }
        if (t == 0) {
            s_gv = v; s_gi = i;
            s_cnt = 0; s_ovf = 0;
            s_bestV = -1.0f; s_bestI = 0x7fffffff;
            if (slot == 0) g_salmax[b] = v;   // exact max saliency
        }
    }
    __syncthreads();

    int winner;
    if (slot == 0) {
        winner = s_gi;   // pre_kernel partials are exact
    } else {
        // Gather candidates recorded by update(slot-1).
        if (t < CHUNKS) {
            int cblk = b * CHUNKS + t;
            int cnt  = g_ccnt[cblk];
            if (cnt > CAP) atomicExch(&s_ovf, 1);
            int m = min(cnt, CAP);
            for (int k = 0; k < m; ++k) {
                int p = atomicAdd(&s_cnt, 1);
                if (p < MAXC) list[p] = g_cand[cblk * CAP + k];
                else atomicExch(&s_ovf, 1);
            }
        }
        __syncthreads();

        if (s_ovf) {   // deterministic fallback: full scan (practically unreachable)
            if (t == 0) s_cnt = 0;
            __syncthreads();
            float thr = s_gv - g_salmax[b] * (float)slot * 3e-3f;
            for (int i = t; i < N_; i += THREADS) {
                if (g_score[b * N_ + i] >= thr) {
                    int p = atomicAdd(&s_cnt, 1);
                    if (p < MAXC) list[p] = i;
                }
            }
            __syncthreads();
        }

        int nc = min(s_cnt, MAXC);
        if (nc == 1) {
            winner = list[0];
        } else {
            // Exact fp32 rescoring of candidates (uniform control flow).
            for (int ci = 0; ci < nc; ++ci) {
                int idx = list[ci];
                float x = f[((size_t)b * N_ + idx) * D_ + t];
                float sal2 = block_reduce_sum(x * x, red);
                float sal  = sqrtf(sal2);
                float fn   = x / fmaxf(sal, EPSN);
                float supp = 1.0f;
                for (int j = 0; j < slot; ++j) {
                    float pj  = fn * g_selhist[((size_t)j * B_ + b) * D_ + t];
                    float sim = block_reduce_sum(pj, red);
                    supp *= (1.0f - fminf(fmaxf(sim, 0.0f), 1.0f));
                }
                if (t == 0) {
                    float scv = sal * supp;
                    if (scv > s_bestV || (scv == s_bestV && idx < s_bestI)) {
                        s_bestV = scv; s_bestI = idx;
                    }
                }
                __syncthreads();
            }
            winner = s_bestI;
        }
    }

    float x = f[((size_t)b * N_ + winner) * D_ + t];
    out[((size_t)b * S_ + slot) * D_ + t] = x;
    float sal2 = block_reduce_sum(x * x, red);
    float inv  = 1.0f / fmaxf(sqrtf(sal2), EPSN);
    g_selhist[((size_t)slot * B_ + b) * D_ + t] = x * inv;   // exact fp32 selnorm
}

// -----------------------------------------------------------------------------
extern "C" void kernel_launch(void* const* d_in, const int* in_sizes, int n_in,
                              void* d_out, int out_size) {
    const float* f = nullptr;
    long best = -1;
    for (int i = 0; i < n_in; ++i) {
        if ((long)in_sizes[i] > best) { best = in_sizes[i]; f = (const float*)d_in[i]; }
    }
    float* out = (float*)d_out;

    pre_kernel<<<B_ * CHUNKS, THREADS>>>(f);
    for (int s = 0; s < S_; ++s) {
        select_kernel<<<B_, THREADS>>>(f, out, s);
        if (s < S_ - 1) update_kernel<<<B_ * CHUNKS, THREADS>>>(s);
    }
}

// round 6
// speedup vs baseline: 3.0426x; 3.0426x over previous
#include <cuda_runtime.h>
#include <cuda_fp16.h>

#define B_ 32
#define N_ 16384
#define D_ 256
#define S_ 8
#define CHUNKS 64
#define ROWS_PER_BLOCK (N_ / CHUNKS)   // 256
#define THREADS 256                    // 8 warps
#define EPSN 1e-12f
#define CAP 16                         // per-block candidate capacity
#define MAXC 256                       // select-side candidate capacity

// ---- scratch (device globals: no allocations allowed) ----
__device__ float  g_score[B_ * N_];                 // running score (approx after s>0)
__device__ __half g_fnorm[(size_t)B_ * N_ * D_];    // normalized rows, fp16 (256 MB)
__device__ float  g_selhist[(size_t)S_ * B_ * D_];  // exact fp32 selnorm history
__device__ float  g_salmax[B_];                     // exact max saliency per batch
__device__ float  g_pval[B_ * CHUNKS];              // per-block max score
__device__ int    g_pidx[B_ * CHUNKS];              // per-block argmax idx (exact from pre)
__device__ int    g_ccnt[B_ * CHUNKS];              // per-block candidate count
__device__ int    g_cand[B_ * CHUNKS * CAP];        // per-block candidate rows
__device__ float  g_cscore[B_ * CHUNKS * CAP];      // per-block candidate approx scores

// Block-wide sum; every thread returns the same value (deterministic order).
__device__ __forceinline__ float block_reduce_sum(float v, float* red) {
    int lane = threadIdx.x & 31, warp = threadIdx.x >> 5;
    #pragma unroll
    for (int o = 16; o; o >>= 1) v += __shfl_xor_sync(0xffffffffu, v, o);
    if (lane == 0) red[warp] = v;
    __syncthreads();
    float tot = red[0] + red[1] + red[2] + red[3]
              + red[4] + red[5] + red[6] + red[7];
    __syncthreads();
    return tot;
}

// -----------------------------------------------------------------------------
// Pass 0 (R3-proven): exact fp32 row norms -> score, fnorm fp16, exact
// per-block argmax. grid = B*CHUNKS x 256; warp per row, 32 rows/warp.
// -----------------------------------------------------------------------------
__global__ void pre_kernel(const float* __restrict__ f) {
    int blk  = blockIdx.x;
    int b    = blk / CHUNKS;
    int c    = blk % CHUNKS;
    int warp = threadIdx.x >> 5;
    int lane = threadIdx.x & 31;
    int row0 = c * ROWS_PER_BLOCK + warp * 32;

    float bestV = -1.0f;
    int   bestI = 0x7fffffff;

    #pragma unroll 2
    for (int r = 0; r < 32; ++r) {
        int row = row0 + r;
        size_t base = ((size_t)b * N_ + row) * D_;
        const float4* p = (const float4*)(f + base);
        float4 a  = p[2 * lane];
        float4 bb = p[2 * lane + 1];
        float s = a.x*a.x + a.y*a.y + a.z*a.z + a.w*a.w
                + bb.x*bb.x + bb.y*bb.y + bb.z*bb.z + bb.w*bb.w;
        #pragma unroll
        for (int o = 16; o; o >>= 1) s += __shfl_xor_sync(0xffffffffu, s, o);
        float nrm = sqrtf(s);
        float inv = 1.0f / fmaxf(nrm, EPSN);

        union { float4 v; __half2 h[4]; } u;
        u.h[0] = __floats2half2_rn(a.x * inv,  a.y * inv);
        u.h[1] = __floats2half2_rn(a.z * inv,  a.w * inv);
        u.h[2] = __floats2half2_rn(bb.x * inv, bb.y * inv);
        u.h[3] = __floats2half2_rn(bb.z * inv, bb.w * inv);
        *(float4*)(g_fnorm + base + (size_t)lane * 8) = u.v;

        if (lane == 0) g_score[b * N_ + row] = nrm;
        if (nrm > bestV) { bestV = nrm; bestI = row; }
    }

    __shared__ float sv[8];
    __shared__ int   si[8];
    if (lane == 0) { sv[warp] = bestV; si[warp] = bestI; }
    __syncthreads();
    if (threadIdx.x == 0) {
        float v = sv[0]; int i = si[0];
        #pragma unroll
        for (int w = 1; w < 8; ++w)
            if (sv[w] > v || (sv[w] == v && si[w] < i)) { v = sv[w]; i = si[w]; }
        g_pval[blk] = v;
        g_pidx[blk] = i;
    }
}

// -----------------------------------------------------------------------------
// Update (suppression for slot s): 2 rows per iter (+unroll) for MLP; fused
// block max + candidate recording (idx AND score) for select(s+1).
// grid = B*CHUNKS x 256.
// -----------------------------------------------------------------------------
__global__ void update_kernel(int s) {
    int blk  = blockIdx.x;
    int b    = blk / CHUNKS;
    int c    = blk % CHUNKS;
    int t    = threadIdx.x;
    int warp = t >> 5;
    int lane = t & 31;

    __shared__ float ssel[D_];
    __shared__ float s_scores[THREADS];
    __shared__ float s_wmax[8];
    __shared__ float s_thr;
    __shared__ int   s_cnt;

    ssel[t] = g_selhist[((size_t)s * B_ + b) * D_ + t];
    __syncthreads();

    float se[8];
    #pragma unroll
    for (int k = 0; k < 8; ++k) se[k] = ssel[lane * 8 + k];

    int row0 = c * ROWS_PER_BLOCK + warp * 32;
    float bestV = -1.0f;

    #pragma unroll 2
    for (int r = 0; r < 32; r += 2) {
        size_t base = ((size_t)b * N_ + row0 + r) * D_ + (size_t)lane * 8;
        float4 raw0 = *(const float4*)(g_fnorm + base);
        float4 raw1 = *(const float4*)(g_fnorm + base + D_);
        float  sc0  = g_score[b * N_ + row0 + r];
        float  sc1  = g_score[b * N_ + row0 + r + 1];

        __half2* h0 = (__half2*)&raw0;
        __half2* h1 = (__half2*)&raw1;
        float d0 = 0.0f, d1 = 0.0f;
        #pragma unroll
        for (int k = 0; k < 4; ++k) {
            float2 a0 = __half22float2(h0[k]);
            float2 a1 = __half22float2(h1[k]);
            d0 = fmaf(a0.x, se[2 * k],     d0);
            d0 = fmaf(a0.y, se[2 * k + 1], d0);
            d1 = fmaf(a1.x, se[2 * k],     d1);
            d1 = fmaf(a1.y, se[2 * k + 1], d1);
        }
        #pragma unroll
        for (int o = 16; o; o >>= 1) {
            d0 += __shfl_xor_sync(0xffffffffu, d0, o);
            d1 += __shfl_xor_sync(0xffffffffu, d1, o);
        }
        float ns0 = sc0 * (1.0f - fminf(fmaxf(d0, 0.0f), 1.0f));
        float ns1 = sc1 * (1.0f - fminf(fmaxf(d1, 0.0f), 1.0f));
        if (lane == 0) {
            g_score[b * N_ + row0 + r]     = ns0;
            g_score[b * N_ + row0 + r + 1] = ns1;
            s_scores[warp * 32 + r]     = ns0;
            s_scores[warp * 32 + r + 1] = ns1;
        }
        bestV = fmaxf(bestV, fmaxf(ns0, ns1));
    }

    if (lane == 0) s_wmax[warp] = bestV;
    __syncthreads();
    if (t == 0) {
        float m = s_wmax[0];
        #pragma unroll
        for (int w = 1; w < 8; ++w) m = fmaxf(m, s_wmax[w]);
        // margin for select(s+1): rigorous 2*eps bound with 3x headroom
        float margin = g_salmax[b] * (float)(s + 1) * 3e-3f;
        s_thr = m - margin;
        s_cnt = 0;
        g_pval[blk] = m;
    }
    __syncthreads();

    float myscore = s_scores[t];
    if (myscore >= s_thr) {
        int p = atomicAdd(&s_cnt, 1);
        if (p < CAP) {
            g_cand[blk * CAP + p]   = c * ROWS_PER_BLOCK + t;
            g_cscore[blk * CAP + p] = myscore;
        }
    }
    __syncthreads();
    if (t == 0) g_ccnt[blk] = s_cnt;   // > CAP signals overflow
}

// -----------------------------------------------------------------------------
// Select(slot): parallel partial reduce -> global approx max; gather recorded
// candidates FILTERED by the global threshold (typically 1 survives); exact
// fp32 verification only when >1. grid = B x 256.
// -----------------------------------------------------------------------------
__global__ void select_kernel(const float* __restrict__ f,
                              float* __restrict__ out, int slot) {
    int b = blockIdx.x;
    int t = threadIdx.x;

    __shared__ float red[8];
    __shared__ float s_gv;
    __shared__ int   s_gi;
    __shared__ int   s_cnt, s_ovf;
    __shared__ int   list[MAXC];
    __shared__ float s_bestV;
    __shared__ int   s_bestI;

    // Parallel reduce of 64 per-block partials with low-idx tiebreak
    // (tiebreak only meaningful for slot==0 where partials are exact).
    if (t < 32) {
        float v  = g_pval[b * CHUNKS + t];      int i  = g_pidx[b * CHUNKS + t];
        float v2 = g_pval[b * CHUNKS + t + 32]; int i2 = g_pidx[b * CHUNKS + t + 32];
        if (v2 > v || (v2 == v && i2 < i)) { v = v2; i = i2; }
        #pragma unroll
        for (int o = 16; o; o >>= 1) {
            float ov = __shfl_xor_sync(0xffffffffu, v, o);
            int   oi = __shfl_xor_sync(0xffffffffu, i, o);
            if (ov > v || (ov == v && oi < i)) { v = ov; i = oi; }
        }
        if (t == 0) {
            s_gv = v; s_gi = i;
            s_cnt = 0; s_ovf = 0;
            s_bestV = -1.0f; s_bestI = 0x7fffffff;
            if (slot == 0) g_salmax[b] = v;   // exact max saliency
        }
    }
    __syncthreads();

    int winner;
    if (slot == 0) {
        winner = s_gi;   // pre_kernel partials are exact
    } else {
        float margin = g_salmax[b] * (float)slot * 3e-3f;
        float thr    = s_gv - margin;   // GLOBAL threshold

        // Gather + filter candidates recorded by update(slot-1).
        if (t < CHUNKS) {
            int cblk = b * CHUNKS + t;
            int cnt  = g_ccnt[cblk];
            if (cnt > CAP) atomicExch(&s_ovf, 1);
            int m = min(cnt, CAP);
            for (int k = 0; k < m; ++k) {
                if (g_cscore[cblk * CAP + k] >= thr) {
                    int p = atomicAdd(&s_cnt, 1);
                    if (p < MAXC) list[p] = g_cand[cblk * CAP + k];
                    else atomicExch(&s_ovf, 1);
                }
            }
        }
        __syncthreads();

        if (s_ovf) {   // deterministic fallback: full scan (practically unreachable)
            if (t == 0) s_cnt = 0;
            __syncthreads();
            for (int i = t; i < N_; i += THREADS) {
                if (g_score[b * N_ + i] >= thr) {
                    int p = atomicAdd(&s_cnt, 1);
                    if (p < MAXC) list[p] = i;
                }
            }
            __syncthreads();
        }

        int nc = min(s_cnt, MAXC);
        if (nc == 1) {
            winner = list[0];
        } else {
            // Exact fp32 rescoring of surviving candidates.
            for (int ci = 0; ci < nc; ++ci) {
                int idx = list[ci];
                float x = f[((size_t)b * N_ + idx) * D_ + t];
                float sal2 = block_reduce_sum(x * x, red);
                float sal  = sqrtf(sal2);
                float fn   = x / fmaxf(sal, EPSN);
                float supp = 1.0f;
                for (int j = 0; j < slot; ++j) {
                    float pj  = fn * g_selhist[((size_t)j * B_ + b) * D_ + t];
                    float sim = block_reduce_sum(pj, red);
                    supp *= (1.0f - fminf(fmaxf(sim, 0.0f), 1.0f));
                }
                if (t == 0) {
                    float scv = sal * supp;
                    if (scv > s_bestV || (scv == s_bestV && idx < s_bestI)) {
                        s_bestV = scv; s_bestI = idx;
                    }
                }
                __syncthreads();
            }
            winner = s_bestI;
        }
    }

    float x = f[((size_t)b * N_ + winner) * D_ + t];
    out[((size_t)b * S_ + slot) * D_ + t] = x;
    float sal2 = block_reduce_sum(x * x, red);
    float inv  = 1.0f / fmaxf(sqrtf(sal2), EPSN);
    g_selhist[((size_t)slot * B_ + b) * D_ + t] = x * inv;   // exact fp32 selnorm
}

// -----------------------------------------------------------------------------
extern "C" void kernel_launch(void* const* d_in, const int* in_sizes, int n_in,
                              void* d_out, int out_size) {
    const float* f = nullptr;
    long best = -1;
    for (int i = 0; i < n_in; ++i) {
        if ((long)in_sizes[i] > best) { best = in_sizes[i]; f = (const float*)d_in[i]; }
    }
    float* out = (float*)d_out;

    pre_kernel<<<B_ * CHUNKS, THREADS>>>(f);
    for (int s = 0; s < S_; ++s) {
        select_kernel<<<B_, THREADS>>>(f, out, s);
        if (s < S_ - 1) update_kernel<<<B_ * CHUNKS, THREADS>>>(s);
    }
}

// round 7
// speedup vs baseline: 3.2294x; 1.0614x over previous
#include <cuda_runtime.h>
#include <cuda_fp16.h>

#define B_ 32
#define N_ 16384
#define D_ 256
#define S_ 8
#define CHUNKS 32
#define ROWS_PER_BLOCK (N_ / CHUNKS)   // 512
#define ROWS_PER_WARP  64
#define THREADS 256                    // 8 warps
#define EPSN 1e-12f
#define BCAP 2048                      // per-batch candidate capacity
#define MAXC 256                       // select-side surviving-candidate capacity

// ---- scratch (device globals: no allocations allowed) ----
__device__ float  g_score[B_ * N_];                 // running score (approx after s>0)
__device__ __half g_fnorm[(size_t)B_ * N_ * D_];    // normalized rows, fp16 (256 MB)
__device__ float  g_selhist[(size_t)S_ * B_ * D_];  // exact fp32 selnorm history
__device__ float  g_salmax[B_];                     // exact max saliency per batch
__device__ float  g_pval[B_ * CHUNKS];              // per-block max (pre only, exact)
__device__ int    g_pidx[B_ * CHUNKS];              // per-block argmax idx (pre only)
__device__ int    g_bcnt[B_];                       // per-batch candidate count
__device__ int    g_bcand[B_ * BCAP];               // per-batch candidate rows
__device__ float  g_bscore[B_ * BCAP];              // per-batch candidate approx scores

// Block-wide sum; every thread returns the same value (deterministic order).
__device__ __forceinline__ float block_reduce_sum(float v, float* red) {
    int lane = threadIdx.x & 31, warp = threadIdx.x >> 5;
    #pragma unroll
    for (int o = 16; o; o >>= 1) v += __shfl_xor_sync(0xffffffffu, v, o);
    if (lane == 0) red[warp] = v;
    __syncthreads();
    float tot = red[0] + red[1] + red[2] + red[3]
              + red[4] + red[5] + red[6] + red[7];
    __syncthreads();
    return tot;
}

__device__ __forceinline__ float block_reduce_max(float v, float* red) {
    int lane = threadIdx.x & 31, warp = threadIdx.x >> 5;
    #pragma unroll
    for (int o = 16; o; o >>= 1) v = fmaxf(v, __shfl_xor_sync(0xffffffffu, v, o));
    if (lane == 0) red[warp] = v;
    __syncthreads();
    float m = fmaxf(fmaxf(fmaxf(red[0], red[1]), fmaxf(red[2], red[3])),
                    fmaxf(fmaxf(red[4], red[5]), fmaxf(red[6], red[7])));
    __syncthreads();
    return m;
}

// -----------------------------------------------------------------------------
// Pass 0: exact fp32 row norms -> score, fnorm fp16, exact per-block argmax.
// grid = B*CHUNKS (=1024) x 256; warp per row, 64 rows/warp.
// -----------------------------------------------------------------------------
__global__ void pre_kernel(const float* __restrict__ f) {
    int blk  = blockIdx.x;
    int b    = blk / CHUNKS;
    int c    = blk % CHUNKS;
    int warp = threadIdx.x >> 5;
    int lane = threadIdx.x & 31;
    int row0 = c * ROWS_PER_BLOCK + warp * ROWS_PER_WARP;

    float bestV = -1.0f;
    int   bestI = 0x7fffffff;

    #pragma unroll 2
    for (int r = 0; r < ROWS_PER_WARP; ++r) {
        int row = row0 + r;
        size_t base = ((size_t)b * N_ + row) * D_;
        const float4* p = (const float4*)(f + base);
        float4 a  = p[2 * lane];
        float4 bb = p[2 * lane + 1];
        float s = a.x*a.x + a.y*a.y + a.z*a.z + a.w*a.w
                + bb.x*bb.x + bb.y*bb.y + bb.z*bb.z + bb.w*bb.w;
        #pragma unroll
        for (int o = 16; o; o >>= 1) s += __shfl_xor_sync(0xffffffffu, s, o);
        float nrm = sqrtf(s);
        float inv = 1.0f / fmaxf(nrm, EPSN);

        union { float4 v; __half2 h[4]; } u;
        u.h[0] = __floats2half2_rn(a.x * inv,  a.y * inv);
        u.h[1] = __floats2half2_rn(a.z * inv,  a.w * inv);
        u.h[2] = __floats2half2_rn(bb.x * inv, bb.y * inv);
        u.h[3] = __floats2half2_rn(bb.z * inv, bb.w * inv);
        *(float4*)(g_fnorm + base + (size_t)lane * 8) = u.v;

        if (lane == 0) g_score[b * N_ + row] = nrm;
        if (nrm > bestV) { bestV = nrm; bestI = row; }
    }

    __shared__ float sv[8];
    __shared__ int   si[8];
    if (lane == 0) { sv[warp] = bestV; si[warp] = bestI; }
    __syncthreads();
    if (threadIdx.x == 0) {
        float v = sv[0]; int i = si[0];
        #pragma unroll
        for (int w = 1; w < 8; ++w)
            if (sv[w] > v || (sv[w] == v && si[w] < i)) { v = sv[w]; i = si[w]; }
        g_pval[blk] = v;
        g_pidx[blk] = i;
    }
}

// -----------------------------------------------------------------------------
// Update (suppression for slot s): 2 rows/iter, block-local threshold, append
// candidates (idx+score) to the per-batch global list for select(s+1).
// grid = B*CHUNKS (=1024) x 256, single wave at 7 blocks/SM.
// -----------------------------------------------------------------------------
__global__ void __launch_bounds__(THREADS, 7) update_kernel(int s) {
    int blk  = blockIdx.x;
    int b    = blk / CHUNKS;
    int c    = blk % CHUNKS;
    int t    = threadIdx.x;
    int warp = t >> 5;
    int lane = t & 31;

    __shared__ float ssel[D_];
    __shared__ float s_scores[ROWS_PER_BLOCK];
    __shared__ float s_wmax[8];
    __shared__ float s_thr;

    ssel[t] = g_selhist[((size_t)s * B_ + b) * D_ + t];
    __syncthreads();

    float se[8];
    #pragma unroll
    for (int k = 0; k < 8; ++k) se[k] = ssel[lane * 8 + k];

    int row0 = c * ROWS_PER_BLOCK + warp * ROWS_PER_WARP;
    float bestV = -1.0f;

    #pragma unroll 2
    for (int r = 0; r < ROWS_PER_WARP; r += 2) {
        size_t base = ((size_t)b * N_ + row0 + r) * D_ + (size_t)lane * 8;
        float4 raw0 = *(const float4*)(g_fnorm + base);
        float4 raw1 = *(const float4*)(g_fnorm + base + D_);
        float  sc0  = g_score[b * N_ + row0 + r];
        float  sc1  = g_score[b * N_ + row0 + r + 1];

        __half2* h0 = (__half2*)&raw0;
        __half2* h1 = (__half2*)&raw1;
        float d0 = 0.0f, d1 = 0.0f;
        #pragma unroll
        for (int k = 0; k < 4; ++k) {
            float2 a0 = __half22float2(h0[k]);
            float2 a1 = __half22float2(h1[k]);
            d0 = fmaf(a0.x, se[2 * k],     d0);
            d0 = fmaf(a0.y, se[2 * k + 1], d0);
            d1 = fmaf(a1.x, se[2 * k],     d1);
            d1 = fmaf(a1.y, se[2 * k + 1], d1);
        }
        #pragma unroll
        for (int o = 16; o; o >>= 1) {
            d0 += __shfl_xor_sync(0xffffffffu, d0, o);
            d1 += __shfl_xor_sync(0xffffffffu, d1, o);
        }
        float ns0 = sc0 * (1.0f - fminf(fmaxf(d0, 0.0f), 1.0f));
        float ns1 = sc1 * (1.0f - fminf(fmaxf(d1, 0.0f), 1.0f));
        if (lane == 0) {
            g_score[b * N_ + row0 + r]              = ns0;
            g_score[b * N_ + row0 + r + 1]          = ns1;
            s_scores[warp * ROWS_PER_WARP + r]      = ns0;
            s_scores[warp * ROWS_PER_WARP + r + 1]  = ns1;
        }
        bestV = fmaxf(bestV, fmaxf(ns0, ns1));
    }

    if (lane == 0) s_wmax[warp] = bestV;
    __syncthreads();
    if (t == 0) {
        float m = s_wmax[0];
        #pragma unroll
        for (int w = 1; w < 8; ++w) m = fmaxf(m, s_wmax[w]);
        // margin for select(s+1): rigorous 2*eps bound with 3x headroom.
        // block-local threshold: superset of the global-margin set.
        s_thr = m - g_salmax[b] * (float)(s + 1) * 3e-3f;
    }
    __syncthreads();

    float thr = s_thr;
    #pragma unroll
    for (int i = t; i < ROWS_PER_BLOCK; i += THREADS) {
        float sc = s_scores[i];
        if (sc >= thr) {
            int p = atomicAdd(&g_bcnt[b], 1);
            if (p < BCAP) {
                g_bcand[b * BCAP + p]  = c * ROWS_PER_BLOCK + i;
                g_bscore[b * BCAP + p] = sc;
            }
        }
    }
}

// -----------------------------------------------------------------------------
// Select(slot): slot 0 uses exact pre partials; slot>=1 reads the per-batch
// candidate list (global max is guaranteed to be in it), filters by global
// threshold, exact fp32 verification only when >1 survives. Resets the
// per-batch counter for the next update pass. grid = B x 256.
// -----------------------------------------------------------------------------
__global__ void select_kernel(const float* __restrict__ f,
                              float* __restrict__ out, int slot) {
    int b = blockIdx.x;
    int t = threadIdx.x;

    __shared__ float red[8];
    __shared__ int   s_cnt, s_ovf;
    __shared__ int   list[MAXC];
    __shared__ float s_bestV;
    __shared__ int   s_bestI;
    __shared__ int   s_win;

    if (t == 0) { s_cnt = 0; s_ovf = 0; s_bestV = -1.0f; s_bestI = 0x7fffffff; }
    __syncthreads();

    int winner;
    if (slot == 0) {
        // exact partials from pre: reduce 32 (val,idx) pairs in warp 0
        if (t < 32) {
            float v = g_pval[b * CHUNKS + t];
            int   i = g_pidx[b * CHUNKS + t];
            #pragma unroll
            for (int o = 16; o; o >>= 1) {
                float ov = __shfl_xor_sync(0xffffffffu, v, o);
                int   oi = __shfl_xor_sync(0xffffffffu, i, o);
                if (ov > v || (ov == v && oi < i)) { v = ov; i = oi; }
            }
            if (t == 0) { s_win = i; g_salmax[b] = v; }
        }
        __syncthreads();
        winner = s_win;
    } else {
        int cnt = g_bcnt[b];
        int m   = min(cnt, BCAP);
        if (cnt > BCAP) { if (t == 0) s_ovf = 1; }

        // max over recorded candidate scores == global approx max
        float lv = -1.0f;
        for (int i = t; i < m; i += THREADS)
            lv = fmaxf(lv, g_bscore[b * BCAP + i]);
        float gmax = block_reduce_max(lv, red);

        float margin = g_salmax[b] * (float)slot * 3e-3f;
        float thr;

        if (s_ovf) {
            // rigorous fallback: true max from full scan, then gather
            lv = -1.0f;
            for (int i = t; i < N_; i += THREADS)
                lv = fmaxf(lv, g_score[b * N_ + i]);
            gmax = block_reduce_max(lv, red);
            thr = gmax - margin;
            for (int i = t; i < N_; i += THREADS) {
                if (g_score[b * N_ + i] >= thr) {
                    int p = atomicAdd(&s_cnt, 1);
                    if (p < MAXC) list[p] = i;
                }
            }
            __syncthreads();
        } else {
            thr = gmax - margin;
            for (int i = t; i < m; i += THREADS) {
                if (g_bscore[b * BCAP + i] >= thr) {
                    int p = atomicAdd(&s_cnt, 1);
                    if (p < MAXC) list[p] = g_bcand[b * BCAP + i];
                }
            }
            __syncthreads();
        }

        int nc = min(s_cnt, MAXC);
        if (nc == 1) {
            winner = list[0];
        } else {
            // exact fp32 rescoring of surviving candidates
            for (int ci = 0; ci < nc; ++ci) {
                int idx = list[ci];
                float x = f[((size_t)b * N_ + idx) * D_ + t];
                float sal2 = block_reduce_sum(x * x, red);
                float sal  = sqrtf(sal2);
                float fn   = x / fmaxf(sal, EPSN);
                float supp = 1.0f;
                for (int j = 0; j < slot; ++j) {
                    float pj  = fn * g_selhist[((size_t)j * B_ + b) * D_ + t];
                    float sim = block_reduce_sum(pj, red);
                    supp *= (1.0f - fminf(fmaxf(sim, 0.0f), 1.0f));
                }
                if (t == 0) {
                    float scv = sal * supp;
                    if (scv > s_bestV || (scv == s_bestV && idx < s_bestI)) {
                        s_bestV = scv; s_bestI = idx;
                    }
                }
                __syncthreads();
            }
            winner = s_bestI;
        }
    }

    // reset per-batch candidate counter for update(slot)'s appends
    if (t == 0) g_bcnt[b] = 0;

    float x = f[((size_t)b * N_ + winner) * D_ + t];
    out[((size_t)b * S_ + slot) * D_ + t] = x;
    float sal2 = block_reduce_sum(x * x, red);
    float inv  = 1.0f / fmaxf(sqrtf(sal2), EPSN);
    g_selhist[((size_t)slot * B_ + b) * D_ + t] = x * inv;   // exact fp32 selnorm
}

// -----------------------------------------------------------------------------
extern "C" void kernel_launch(void* const* d_in, const int* in_sizes, int n_in,
                              void* d_out, int out_size) {
    const float* f = nullptr;
    long best = -1;
    for (int i = 0; i < n_in; ++i) {
        if ((long)in_sizes[i] > best) { best = in_sizes[i]; f = (const float*)d_in[i]; }
    }
    float* out = (float*)d_out;

    pre_kernel<<<B_ * CHUNKS, THREADS>>>(f);
    for (int s = 0; s < S_; ++s) {
        select_kernel<<<B_, THREADS>>>(f, out, s);
        if (s < S_ - 1) update_kernel<<<B_ * CHUNKS, THREADS>>>(s);
    }
}